// round 1
// baseline (speedup 1.0000x reference)
#include <cuda_runtime.h>

// ----------------------------------------------------------------------------
// SymplecticGyroceptron: 8 inverse psi Henon layers, circle action,
// 8 forward psi + 8 forward NI Henon layers. Each Henon layer = 4 sub-steps,
// each sub-step evaluates grad_V = 64-neuron tanh-MLP gradient on a 2-vector.
//
// tanh reformulation: with p = y.w + b,
//   r = 1/(1 + e^{2p}),  tanh(p) = 1 - 2r,  1 - tanh^2(p) = 4(r - r^2)
// Constants baked at prep time into packed float4 per (layer, neuron):
//   w.x = K*W_in[0][j], w.y = K*W_in[1][j], w.z = K*b[j], w.w = (4*eps/K)*W_out[j]
// where K = 2/ln2, so e^{2p} = ex2(fma(y0,w.x,fma(y1,w.y,w.z))).
// grad contribution: g += (w.w * (r - r^2)) * w.{x,y}   (== eps*(1-t^2)*wout*win)
// ----------------------------------------------------------------------------

#define NEUR 64
#define NLAYERS 16   // 0..7 = psi (eps=1), 8..15 = ni (eps=0.01)

__device__ float4 g_packed[NLAYERS * NEUR];
__device__ float2 g_eta[NLAYERS];
__device__ float2 g_cs;

__global__ void prep_kernel(const float* __restrict__ theta0,
                            const float* __restrict__ psi_Win,
                            const float* __restrict__ psi_Wout,
                            const float* __restrict__ psi_b,
                            const float* __restrict__ psi_eta,
                            const float* __restrict__ ni_Win,
                            const float* __restrict__ ni_Wout,
                            const float* __restrict__ ni_b,
                            const float* __restrict__ ni_eta)
{
    const float Kc = 2.885390081777927f;   // 2/ln(2)
    const float S  = 1.3862943611198906f;  // 4/Kc = 2*ln(2)
    int t = threadIdx.x;
    if (t < NLAYERS * NEUR) {
        int l = t >> 6;
        int j = t & 63;
        const float *Win, *Wout, *b;
        float eps;
        int i;
        if (l < 8) { i = l;     Win = psi_Win; Wout = psi_Wout; b = psi_b; eps = 1.0f;  }
        else       { i = l - 8; Win = ni_Win;  Wout = ni_Wout;  b = ni_b;  eps = 0.01f; }
        float w0 = Win[i * 128 + j];        // W_in[i][0][j]
        float w1 = Win[i * 128 + 64 + j];   // W_in[i][1][j]
        float bb = b[i * 64 + j];           // b_in[i][0][j]
        float wo = Wout[i * 64 + j];        // W_out[i][j][0]
        g_packed[t] = make_float4(Kc * w0, Kc * w1, Kc * bb, S * eps * wo);
    }
    if (t < NLAYERS) {
        const float* e = (t < 8) ? (psi_eta + t * 2) : (ni_eta + (t - 8) * 2);
        g_eta[t] = make_float2(e[0], e[1]);
    }
    if (t == 0) {
        float th = theta0[0];
        g_cs = make_float2(cosf(th), sinf(th));
    }
}

// grad_V (with eps and all constants pre-baked into sw)
__device__ __forceinline__ void grad2(const float4* __restrict__ sw,
                                      float y0, float y1,
                                      float& g0, float& g1)
{
    float a0 = 0.f, a1 = 0.f, b0 = 0.f, b1 = 0.f;
#pragma unroll
    for (int j = 0; j < NEUR; j += 2) {
        {
            float4 w = sw[j];
            float pre = fmaf(y0, w.x, fmaf(y1, w.y, w.z));
            float e;  asm("ex2.approx.f32 %0, %1;" : "=f"(e) : "f"(pre));
            float d = e + 1.0f;
            float r;  asm("rcp.approx.f32 %0, %1;" : "=f"(r) : "f"(d));
            float u = fmaf(-r, r, r);        // r - r^2
            float sc = u * w.w;
            a0 = fmaf(sc, w.x, a0);
            a1 = fmaf(sc, w.y, a1);
        }
        {
            float4 w = sw[j + 1];
            float pre = fmaf(y0, w.x, fmaf(y1, w.y, w.z));
            float e;  asm("ex2.approx.f32 %0, %1;" : "=f"(e) : "f"(pre));
            float d = e + 1.0f;
            float r;  asm("rcp.approx.f32 %0, %1;" : "=f"(r) : "f"(d));
            float u = fmaf(-r, r, r);
            float sc = u * w.w;
            b0 = fmaf(sc, w.x, b0);
            b1 = fmaf(sc, w.y, b1);
        }
    }
    g0 = a0 + b0;
    g1 = a1 + b1;
}

__global__ void __launch_bounds__(256)
gyro_kernel(const float4* __restrict__ rin, float4* __restrict__ out, int B)
{
    __shared__ float4 sw[NLAYERS * NEUR];
    __shared__ float2 seta[NLAYERS];
    __shared__ float2 scs;

    for (int i = threadIdx.x; i < NLAYERS * NEUR; i += blockDim.x)
        sw[i] = g_packed[i];
    if (threadIdx.x < NLAYERS) seta[threadIdx.x] = g_eta[threadIdx.x];
    if (threadIdx.x == 0)      scs = g_cs;
    __syncthreads();

    int idx = blockIdx.x * blockDim.x + threadIdx.x;
    if (idx >= B) return;

    float4 z = rin[idx];
    float x0 = z.x, x1 = z.y, y0 = z.z, y1 = z.w;

    // ---- inverse psi layers, i = 7 .. 0, eps = 1 ----
    for (int l = 7; l >= 0; --l) {
        float e0 = seta[l].x, e1 = seta[l].y;
        const float4* w = &sw[l * NEUR];
#pragma unroll 1
        for (int k = 0; k < 4; ++k) {
            float yn0 = x0 - e0, yn1 = x1 - e1;
            float g0, g1;
            grad2(w, yn0, yn1, g0, g1);
            float nx0 = g0 - y0, nx1 = g1 - y1;
            y0 = yn0; y1 = yn1;
            x0 = nx0; x1 = nx1;
        }
    }

    // ---- circle action ----
    {
        float c = scs.x, s = scs.y;
        float q1 = x0, p1 = y0;
        x0 = fmaf(c, q1, s * p1);
        y0 = fmaf(c, p1, -s * q1);
    }

    // ---- forward layers: l = 0..7 psi (eps=1), l = 8..15 ni (eps=0.01, baked) ----
    for (int l = 0; l < NLAYERS; ++l) {
        float e0 = seta[l].x, e1 = seta[l].y;
        const float4* w = &sw[l * NEUR];
#pragma unroll 1
        for (int k = 0; k < 4; ++k) {
            float g0, g1;
            grad2(w, y0, y1, g0, g1);
            float nx0 = y0 + e0, nx1 = y1 + e1;
            float ny0 = g0 - x0, ny1 = g1 - x1;
            x0 = nx0; x1 = nx1;
            y0 = ny0; y1 = ny1;
        }
    }

    out[idx] = make_float4(x0, x1, y0, y1);
}

extern "C" void kernel_launch(void* const* d_in, const int* in_sizes, int n_in,
                              void* d_out, int out_size)
{
    const float* r        = (const float*)d_in[0];
    const float* theta0   = (const float*)d_in[1];
    const float* psi_Win  = (const float*)d_in[2];
    const float* psi_Wout = (const float*)d_in[3];
    const float* psi_b    = (const float*)d_in[4];
    const float* psi_eta  = (const float*)d_in[5];
    const float* ni_Win   = (const float*)d_in[6];
    const float* ni_Wout  = (const float*)d_in[7];
    const float* ni_b     = (const float*)d_in[8];
    const float* ni_eta   = (const float*)d_in[9];

    int B = in_sizes[0] / 4;

    prep_kernel<<<1, 1024>>>(theta0, psi_Win, psi_Wout, psi_b, psi_eta,
                             ni_Win, ni_Wout, ni_b, ni_eta);

    int threads = 256;
    int blocks = (B + threads - 1) / threads;
    gyro_kernel<<<blocks, threads>>>((const float4*)r, (float4*)d_out, B);
}

// round 2
// speedup vs baseline: 2.5495x; 2.5495x over previous
#include <cuda_runtime.h>

// ----------------------------------------------------------------------------
// SymplecticGyroceptron: 8 inverse psi Henon layers, circle action,
// 8 forward psi + 8 forward NI Henon layers. Each Henon layer = 4 sub-steps,
// each sub-step evaluates grad_V = 64-neuron tanh-MLP gradient on a 2-vector.
//
// tanh reformulation: with p = y.w + b,
//   r = 1/(1 + e^{2p}),  tanh(p) = 1 - 2r,  1 - tanh^2(p) = 4(r - r^2)
// Constants baked at prep time into packed float4 per (layer, neuron):
//   w.x = K*W_in[0][j], w.y = K*W_in[1][j], w.z = K*b[j], w.w = (4*eps/K)*W_out[j]
// where K = 2/ln2, so e^{2p} = ex2(fma(y0,w.x,fma(y1,w.y,w.z))).
// grad contribution: g += (w.w * (r - r^2)) * w.{x,y}   (== eps*(1-t^2)*wout*win)
//
// R1 change: unroll 8 (not 64) in grad2 + __launch_bounds__(256,4) to cap
// registers at 64 -> 32 warps/SM (was 255 regs / 8 warps / occ 12%).
// ----------------------------------------------------------------------------

#define NEUR 64
#define NLAYERS 16   // 0..7 = psi (eps=1), 8..15 = ni (eps=0.01)

__device__ float4 g_packed[NLAYERS * NEUR];
__device__ float2 g_eta[NLAYERS];
__device__ float2 g_cs;

__global__ void prep_kernel(const float* __restrict__ theta0,
                            const float* __restrict__ psi_Win,
                            const float* __restrict__ psi_Wout,
                            const float* __restrict__ psi_b,
                            const float* __restrict__ psi_eta,
                            const float* __restrict__ ni_Win,
                            const float* __restrict__ ni_Wout,
                            const float* __restrict__ ni_b,
                            const float* __restrict__ ni_eta)
{
    const float Kc = 2.885390081777927f;   // 2/ln(2)
    const float S  = 1.3862943611198906f;  // 4/Kc = 2*ln(2)
    int t = threadIdx.x;
    if (t < NLAYERS * NEUR) {
        int l = t >> 6;
        int j = t & 63;
        const float *Win, *Wout, *b;
        float eps;
        int i;
        if (l < 8) { i = l;     Win = psi_Win; Wout = psi_Wout; b = psi_b; eps = 1.0f;  }
        else       { i = l - 8; Win = ni_Win;  Wout = ni_Wout;  b = ni_b;  eps = 0.01f; }
        float w0 = Win[i * 128 + j];        // W_in[i][0][j]
        float w1 = Win[i * 128 + 64 + j];   // W_in[i][1][j]
        float bb = b[i * 64 + j];           // b_in[i][0][j]
        float wo = Wout[i * 64 + j];        // W_out[i][j][0]
        g_packed[t] = make_float4(Kc * w0, Kc * w1, Kc * bb, S * eps * wo);
    }
    if (t < NLAYERS) {
        const float* e = (t < 8) ? (psi_eta + t * 2) : (ni_eta + (t - 8) * 2);
        g_eta[t] = make_float2(e[0], e[1]);
    }
    if (t == 0) {
        float th = theta0[0];
        g_cs = make_float2(cosf(th), sinf(th));
    }
}

// grad_V (with eps and all constants pre-baked into sw).
// Unroll 8: keeps ~8 float4 weight loads in flight (enough ILP to cover the
// ex2->add->rcp->fma chain) without exploding register pressure.
__device__ __forceinline__ void grad2(const float4* __restrict__ sw,
                                      float y0, float y1,
                                      float& g0, float& g1)
{
    float a0 = 0.f, a1 = 0.f, b0 = 0.f, b1 = 0.f;
#pragma unroll 8
    for (int j = 0; j < NEUR; j += 2) {
        {
            float4 w = sw[j];
            float pre = fmaf(y0, w.x, fmaf(y1, w.y, w.z));
            float e;  asm("ex2.approx.f32 %0, %1;" : "=f"(e) : "f"(pre));
            float d = e + 1.0f;
            float r;  asm("rcp.approx.f32 %0, %1;" : "=f"(r) : "f"(d));
            float u = fmaf(-r, r, r);        // r - r^2
            float sc = u * w.w;
            a0 = fmaf(sc, w.x, a0);
            a1 = fmaf(sc, w.y, a1);
        }
        {
            float4 w = sw[j + 1];
            float pre = fmaf(y0, w.x, fmaf(y1, w.y, w.z));
            float e;  asm("ex2.approx.f32 %0, %1;" : "=f"(e) : "f"(pre));
            float d = e + 1.0f;
            float r;  asm("rcp.approx.f32 %0, %1;" : "=f"(r) : "f"(d));
            float u = fmaf(-r, r, r);
            float sc = u * w.w;
            b0 = fmaf(sc, w.x, b0);
            b1 = fmaf(sc, w.y, b1);
        }
    }
    g0 = a0 + b0;
    g1 = a1 + b1;
}

__global__ void __launch_bounds__(256, 4)
gyro_kernel(const float4* __restrict__ rin, float4* __restrict__ out, int B)
{
    __shared__ float4 sw[NLAYERS * NEUR];
    __shared__ float2 seta[NLAYERS];
    __shared__ float2 scs;

    for (int i = threadIdx.x; i < NLAYERS * NEUR; i += blockDim.x)
        sw[i] = g_packed[i];
    if (threadIdx.x < NLAYERS) seta[threadIdx.x] = g_eta[threadIdx.x];
    if (threadIdx.x == 0)      scs = g_cs;
    __syncthreads();

    int idx = blockIdx.x * blockDim.x + threadIdx.x;
    if (idx >= B) return;

    float4 z = rin[idx];
    float x0 = z.x, x1 = z.y, y0 = z.z, y1 = z.w;

    // ---- inverse psi layers, i = 7 .. 0, eps = 1 ----
    for (int l = 7; l >= 0; --l) {
        float e0 = seta[l].x, e1 = seta[l].y;
        const float4* w = &sw[l * NEUR];
#pragma unroll 1
        for (int k = 0; k < 4; ++k) {
            float yn0 = x0 - e0, yn1 = x1 - e1;
            float g0, g1;
            grad2(w, yn0, yn1, g0, g1);
            float nx0 = g0 - y0, nx1 = g1 - y1;
            y0 = yn0; y1 = yn1;
            x0 = nx0; x1 = nx1;
        }
    }

    // ---- circle action ----
    {
        float c = scs.x, s = scs.y;
        float q1 = x0, p1 = y0;
        x0 = fmaf(c, q1, s * p1);
        y0 = fmaf(c, p1, -s * q1);
    }

    // ---- forward layers: l = 0..7 psi (eps=1), l = 8..15 ni (eps=0.01, baked) ----
    for (int l = 0; l < NLAYERS; ++l) {
        float e0 = seta[l].x, e1 = seta[l].y;
        const float4* w = &sw[l * NEUR];
#pragma unroll 1
        for (int k = 0; k < 4; ++k) {
            float g0, g1;
            grad2(w, y0, y1, g0, g1);
            float nx0 = y0 + e0, nx1 = y1 + e1;
            float ny0 = g0 - x0, ny1 = g1 - x1;
            x0 = nx0; x1 = nx1;
            y0 = ny0; y1 = ny1;
        }
    }

    out[idx] = make_float4(x0, x1, y0, y1);
}

extern "C" void kernel_launch(void* const* d_in, const int* in_sizes, int n_in,
                              void* d_out, int out_size)
{
    const float* r        = (const float*)d_in[0];
    const float* theta0   = (const float*)d_in[1];
    const float* psi_Win  = (const float*)d_in[2];
    const float* psi_Wout = (const float*)d_in[3];
    const float* psi_b    = (const float*)d_in[4];
    const float* psi_eta  = (const float*)d_in[5];
    const float* ni_Win   = (const float*)d_in[6];
    const float* ni_Wout  = (const float*)d_in[7];
    const float* ni_b     = (const float*)d_in[8];
    const float* ni_eta   = (const float*)d_in[9];

    int B = in_sizes[0] / 4;

    prep_kernel<<<1, 1024>>>(theta0, psi_Win, psi_Wout, psi_b, psi_eta,
                             ni_Win, ni_Wout, ni_b, ni_eta);

    int threads = 256;
    int blocks = (B + threads - 1) / threads;
    gyro_kernel<<<blocks, threads>>>((const float4*)r, (float4*)d_out, B);
}

// round 3
// speedup vs baseline: 4.2706x; 1.6751x over previous
#include <cuda_runtime.h>

// ----------------------------------------------------------------------------
// SymplecticGyroceptron — R3: single-MUFU neuron via tanh.approx.f32.
//
// grad_V_j contribution:  g += eps*(1 - tanh(p)^2) * Wout_j * Win_j
// with p = y0*Win0_j + y1*Win1_j + b_j.
// Prep bakes eps*Wout_j into the input weights:
//   swA[j] = (Win0_j, Win1_j, b_j, eps*Wout_j*Win0_j)
//   swB[j] =  eps*Wout_j*Win1_j
// Per neuron: LDS.128 + LDS.32, 2 FMA (pre), 1 MUFU (tanh), 1 FMA (1-t^2),
// 2 FMA (accumulate)  ->  5 FMA-class + 1 MUFU  (was 7 FMA + 2 MUFU).
// ----------------------------------------------------------------------------

#define NEUR 64
#define NLAYERS 16   // 0..7 = psi (eps=1), 8..15 = ni (eps=0.01)

__device__ float4 g_packedA[NLAYERS * NEUR];
__device__ float  g_packedB[NLAYERS * NEUR];
__device__ float2 g_eta[NLAYERS];
__device__ float2 g_cs;

__global__ void prep_kernel(const float* __restrict__ theta0,
                            const float* __restrict__ psi_Win,
                            const float* __restrict__ psi_Wout,
                            const float* __restrict__ psi_b,
                            const float* __restrict__ psi_eta,
                            const float* __restrict__ ni_Win,
                            const float* __restrict__ ni_Wout,
                            const float* __restrict__ ni_b,
                            const float* __restrict__ ni_eta)
{
    int t = threadIdx.x;
    if (t < NLAYERS * NEUR) {
        int l = t >> 6;
        int j = t & 63;
        const float *Win, *Wout, *b;
        float eps;
        int i;
        if (l < 8) { i = l;     Win = psi_Win; Wout = psi_Wout; b = psi_b; eps = 1.0f;  }
        else       { i = l - 8; Win = ni_Win;  Wout = ni_Wout;  b = ni_b;  eps = 0.01f; }
        float w0 = Win[i * 128 + j];        // W_in[i][0][j]
        float w1 = Win[i * 128 + 64 + j];   // W_in[i][1][j]
        float bb = b[i * 64 + j];           // b_in[i][0][j]
        float wo = Wout[i * 64 + j] * eps;  // eps * W_out[i][j][0]
        g_packedA[t] = make_float4(w0, w1, bb, wo * w0);
        g_packedB[t] = wo * w1;
    }
    if (t < NLAYERS) {
        const float* e = (t < 8) ? (psi_eta + t * 2) : (ni_eta + (t - 8) * 2);
        g_eta[t] = make_float2(e[0], e[1]);
    }
    if (t == 0) {
        float th = theta0[0];
        g_cs = make_float2(cosf(th), sinf(th));
    }
}

// grad_V with all constants pre-baked. Two accumulator pairs for ILP; unroll 8
// keeps ~8 weight fetches in flight without register blowup.
__device__ __forceinline__ void grad2(const float4* __restrict__ swA,
                                      const float*  __restrict__ swB,
                                      float y0, float y1,
                                      float& g0, float& g1)
{
    float a0 = 0.f, a1 = 0.f, b0 = 0.f, b1 = 0.f;
#pragma unroll 8
    for (int j = 0; j < NEUR; j += 2) {
        {
            float4 w  = swA[j];
            float  wy = swB[j];
            float pre = fmaf(y0, w.x, fmaf(y1, w.y, w.z));
            float t;  asm("tanh.approx.f32 %0, %1;" : "=f"(t) : "f"(pre));
            float u = fmaf(-t, t, 1.0f);     // 1 - t^2
            a0 = fmaf(u, w.w, a0);
            a1 = fmaf(u, wy,  a1);
        }
        {
            float4 w  = swA[j + 1];
            float  wy = swB[j + 1];
            float pre = fmaf(y0, w.x, fmaf(y1, w.y, w.z));
            float t;  asm("tanh.approx.f32 %0, %1;" : "=f"(t) : "f"(pre));
            float u = fmaf(-t, t, 1.0f);
            b0 = fmaf(u, w.w, b0);
            b1 = fmaf(u, wy,  b1);
        }
    }
    g0 = a0 + b0;
    g1 = a1 + b1;
}

__global__ void __launch_bounds__(256, 4)
gyro_kernel(const float4* __restrict__ rin, float4* __restrict__ out, int B)
{
    __shared__ float4 swA[NLAYERS * NEUR];
    __shared__ float  swB[NLAYERS * NEUR];
    __shared__ float2 seta[NLAYERS];
    __shared__ float2 scs;

    for (int i = threadIdx.x; i < NLAYERS * NEUR; i += blockDim.x) {
        swA[i] = g_packedA[i];
        swB[i] = g_packedB[i];
    }
    if (threadIdx.x < NLAYERS) seta[threadIdx.x] = g_eta[threadIdx.x];
    if (threadIdx.x == 0)      scs = g_cs;
    __syncthreads();

    int idx = blockIdx.x * blockDim.x + threadIdx.x;
    if (idx >= B) return;

    float4 z = rin[idx];
    float x0 = z.x, x1 = z.y, y0 = z.z, y1 = z.w;

    // ---- inverse psi layers, i = 7 .. 0, eps = 1 ----
    for (int l = 7; l >= 0; --l) {
        float e0 = seta[l].x, e1 = seta[l].y;
        const float4* wA = &swA[l * NEUR];
        const float*  wB = &swB[l * NEUR];
#pragma unroll 1
        for (int k = 0; k < 4; ++k) {
            float yn0 = x0 - e0, yn1 = x1 - e1;
            float g0, g1;
            grad2(wA, wB, yn0, yn1, g0, g1);
            float nx0 = g0 - y0, nx1 = g1 - y1;
            y0 = yn0; y1 = yn1;
            x0 = nx0; x1 = nx1;
        }
    }

    // ---- circle action ----
    {
        float c = scs.x, s = scs.y;
        float q1 = x0, p1 = y0;
        x0 = fmaf(c, q1, s * p1);
        y0 = fmaf(c, p1, -s * q1);
    }

    // ---- forward layers: l = 0..7 psi (eps=1), l = 8..15 ni (eps=0.01, baked) ----
    for (int l = 0; l < NLAYERS; ++l) {
        float e0 = seta[l].x, e1 = seta[l].y;
        const float4* wA = &swA[l * NEUR];
        const float*  wB = &swB[l * NEUR];
#pragma unroll 1
        for (int k = 0; k < 4; ++k) {
            float g0, g1;
            grad2(wA, wB, y0, y1, g0, g1);
            float nx0 = y0 + e0, nx1 = y1 + e1;
            float ny0 = g0 - x0, ny1 = g1 - x1;
            x0 = nx0; x1 = nx1;
            y0 = ny0; y1 = ny1;
        }
    }

    out[idx] = make_float4(x0, x1, y0, y1);
}

extern "C" void kernel_launch(void* const* d_in, const int* in_sizes, int n_in,
                              void* d_out, int out_size)
{
    const float* r        = (const float*)d_in[0];
    const float* theta0   = (const float*)d_in[1];
    const float* psi_Win  = (const float*)d_in[2];
    const float* psi_Wout = (const float*)d_in[3];
    const float* psi_b    = (const float*)d_in[4];
    const float* psi_eta  = (const float*)d_in[5];
    const float* ni_Win   = (const float*)d_in[6];
    const float* ni_Wout  = (const float*)d_in[7];
    const float* ni_b     = (const float*)d_in[8];
    const float* ni_eta   = (const float*)d_in[9];

    int B = in_sizes[0] / 4;

    prep_kernel<<<1, 1024>>>(theta0, psi_Win, psi_Wout, psi_b, psi_eta,
                             ni_Win, ni_Wout, ni_b, ni_eta);

    int threads = 256;
    int blocks = (B + threads - 1) / threads;
    gyro_kernel<<<blocks, threads>>>((const float4*)r, (float4*)d_out, B);
}

// round 4
// speedup vs baseline: 5.8283x; 1.3648x over previous
#include <cuda_runtime.h>

// ----------------------------------------------------------------------------
// SymplecticGyroceptron — R4: 2 points/thread + fma.rn.f32x2 packed math.
//
// Per neuron j (weights uniform across threads, broadcast from shared):
//   p = y0*wx + y1*wy + b          (scalar FMA x2 per point; tanh needs scalars)
//   t = tanh.approx(p)             (1 MUFU per point — binding pipe)
//   t2m = t*t - 1                  (one FFMA2 on packed (tA,tB))
//   g0 += t2m * (-eps*wout*wx)     (FFMA2, negated weight baked at prep)
//   g1 += t2m * (-eps*wout*wy)     (FFMA2)
// Shared per neuron: float4 (wx, wy, b, -eps*wout*wx) + float (-eps*wout*wy)
// -> 2 LDS per neuron serving 2 points (halves L1 wavefront pressure, which
//    was the R3 bottleneck at 80.6%).
// ----------------------------------------------------------------------------

#define NEUR 64
#define NLAYERS 16   // 0..7 = psi (eps=1), 8..15 = ni (eps=0.01)

__device__ float4 g_packedA[NLAYERS * NEUR];
__device__ float  g_packedB[NLAYERS * NEUR];
__device__ float2 g_eta[NLAYERS];
__device__ float2 g_cs;

__global__ void prep_kernel(const float* __restrict__ theta0,
                            const float* __restrict__ psi_Win,
                            const float* __restrict__ psi_Wout,
                            const float* __restrict__ psi_b,
                            const float* __restrict__ psi_eta,
                            const float* __restrict__ ni_Win,
                            const float* __restrict__ ni_Wout,
                            const float* __restrict__ ni_b,
                            const float* __restrict__ ni_eta)
{
    int t = threadIdx.x;
    if (t < NLAYERS * NEUR) {
        int l = t >> 6;
        int j = t & 63;
        const float *Win, *Wout, *b;
        float eps;
        int i;
        if (l < 8) { i = l;     Win = psi_Win; Wout = psi_Wout; b = psi_b; eps = 1.0f;  }
        else       { i = l - 8; Win = ni_Win;  Wout = ni_Wout;  b = ni_b;  eps = 0.01f; }
        float w0 = Win[i * 128 + j];        // W_in[i][0][j]
        float w1 = Win[i * 128 + 64 + j];   // W_in[i][1][j]
        float bb = b[i * 64 + j];           // b_in[i][0][j]
        float wo = -Wout[i * 64 + j] * eps; // NEGATED eps * W_out  (t^2-1 trick)
        g_packedA[t] = make_float4(w0, w1, bb, wo * w0);
        g_packedB[t] = wo * w1;
    }
    if (t < NLAYERS) {
        const float* e = (t < 8) ? (psi_eta + t * 2) : (ni_eta + (t - 8) * 2);
        g_eta[t] = make_float2(e[0], e[1]);
    }
    if (t == 0) {
        float th = theta0[0];
        g_cs = make_float2(cosf(th), sinf(th));
    }
}

// ---- f32x2 helpers ---------------------------------------------------------
typedef unsigned long long u64;

__device__ __forceinline__ u64 pack2(float lo, float hi) {
    u64 d; asm("mov.b64 %0, {%1, %2};" : "=l"(d) : "f"(lo), "f"(hi)); return d;
}
__device__ __forceinline__ void unpack2(u64 d, float& lo, float& hi) {
    asm("mov.b64 {%0, %1}, %2;" : "=f"(lo), "=f"(hi) : "l"(d));
}
__device__ __forceinline__ u64 ffma2(u64 a, u64 b, u64 c) {
    u64 d; asm("fma.rn.f32x2 %0, %1, %2, %3;" : "=l"(d) : "l"(a), "l"(b), "l"(c));
    return d;
}
__device__ __forceinline__ float tanh_ap(float x) {
    float t; asm("tanh.approx.f32 %0, %1;" : "=f"(t) : "f"(x)); return t;
}

// grad_V for two points simultaneously. Accumulators packed (A in lo, B in hi).
__device__ __forceinline__ void grad2x2(const float4* __restrict__ swA,
                                        const float*  __restrict__ swB,
                                        float yA0, float yA1,
                                        float yB0, float yB1,
                                        float& gA0, float& gA1,
                                        float& gB0, float& gB1)
{
    const u64 NEG1 = pack2(-1.0f, -1.0f);
    u64 acc0a = 0ull, acc1a = 0ull, acc0b = 0ull, acc1b = 0ull;  // (0.f,0.f) packed
#pragma unroll 4
    for (int j = 0; j < NEUR; j += 2) {
        {
            float4 w  = swA[j];
            float  wy = swB[j];
            float pA = fmaf(yA0, w.x, fmaf(yA1, w.y, w.z));
            float pB = fmaf(yB0, w.x, fmaf(yB1, w.y, w.z));
            float tA = tanh_ap(pA);
            float tB = tanh_ap(pB);
            u64 tp  = pack2(tA, tB);
            u64 t2m = ffma2(tp, tp, NEG1);        // t^2 - 1
            acc0a = ffma2(t2m, pack2(w.w, w.w), acc0a);
            acc1a = ffma2(t2m, pack2(wy,  wy ), acc1a);
        }
        {
            float4 w  = swA[j + 1];
            float  wy = swB[j + 1];
            float pA = fmaf(yA0, w.x, fmaf(yA1, w.y, w.z));
            float pB = fmaf(yB0, w.x, fmaf(yB1, w.y, w.z));
            float tA = tanh_ap(pA);
            float tB = tanh_ap(pB);
            u64 tp  = pack2(tA, tB);
            u64 t2m = ffma2(tp, tp, NEG1);
            acc0b = ffma2(t2m, pack2(w.w, w.w), acc0b);
            acc1b = ffma2(t2m, pack2(wy,  wy ), acc1b);
        }
    }
    float a0A, a0B, b0A, b0B, a1A, a1B, b1A, b1B;
    unpack2(acc0a, a0A, a0B); unpack2(acc0b, b0A, b0B);
    unpack2(acc1a, a1A, a1B); unpack2(acc1b, b1A, b1B);
    gA0 = a0A + b0A;  gB0 = a0B + b0B;
    gA1 = a1A + b1A;  gB1 = a1B + b1B;
}

__global__ void __launch_bounds__(256, 3)
gyro_kernel(const float4* __restrict__ rin, float4* __restrict__ out,
            int B, int half)
{
    __shared__ float4 swA[NLAYERS * NEUR];
    __shared__ float  swB[NLAYERS * NEUR];
    __shared__ float2 seta[NLAYERS];
    __shared__ float2 scs;

    for (int i = threadIdx.x; i < NLAYERS * NEUR; i += blockDim.x) {
        swA[i] = g_packedA[i];
        swB[i] = g_packedB[i];
    }
    if (threadIdx.x < NLAYERS) seta[threadIdx.x] = g_eta[threadIdx.x];
    if (threadIdx.x == 0)      scs = g_cs;
    __syncthreads();

    int idx = blockIdx.x * blockDim.x + threadIdx.x;
    if (idx >= half) return;
    int idx2 = idx + half;
    bool hasB = (idx2 < B);
    int i2 = hasB ? idx2 : idx;

    float4 zA = rin[idx];
    float4 zB = rin[i2];
    float xA0 = zA.x, xA1 = zA.y, yA0 = zA.z, yA1 = zA.w;
    float xB0 = zB.x, xB1 = zB.y, yB0 = zB.z, yB1 = zB.w;

    // ---- inverse psi layers, l = 7 .. 0 ----
    for (int l = 7; l >= 0; --l) {
        float e0 = seta[l].x, e1 = seta[l].y;
        const float4* wA = &swA[l * NEUR];
        const float*  wB = &swB[l * NEUR];
#pragma unroll 1
        for (int k = 0; k < 4; ++k) {
            float ynA0 = xA0 - e0, ynA1 = xA1 - e1;
            float ynB0 = xB0 - e0, ynB1 = xB1 - e1;
            float gA0, gA1, gB0, gB1;
            grad2x2(wA, wB, ynA0, ynA1, ynB0, ynB1, gA0, gA1, gB0, gB1);
            float nxA0 = gA0 - yA0, nxA1 = gA1 - yA1;
            float nxB0 = gB0 - yB0, nxB1 = gB1 - yB1;
            yA0 = ynA0; yA1 = ynA1; xA0 = nxA0; xA1 = nxA1;
            yB0 = ynB0; yB1 = ynB1; xB0 = nxB0; xB1 = nxB1;
        }
    }

    // ---- circle action ----
    {
        float c = scs.x, s = scs.y;
        float q1 = xA0, p1 = yA0;
        xA0 = fmaf(c, q1, s * p1);
        yA0 = fmaf(c, p1, -s * q1);
        q1 = xB0; p1 = yB0;
        xB0 = fmaf(c, q1, s * p1);
        yB0 = fmaf(c, p1, -s * q1);
    }

    // ---- forward layers: l = 0..7 psi, l = 8..15 ni ----
    for (int l = 0; l < NLAYERS; ++l) {
        float e0 = seta[l].x, e1 = seta[l].y;
        const float4* wA = &swA[l * NEUR];
        const float*  wB = &swB[l * NEUR];
#pragma unroll 1
        for (int k = 0; k < 4; ++k) {
            float gA0, gA1, gB0, gB1;
            grad2x2(wA, wB, yA0, yA1, yB0, yB1, gA0, gA1, gB0, gB1);
            float nxA0 = yA0 + e0, nxA1 = yA1 + e1;
            float nyA0 = gA0 - xA0, nyA1 = gA1 - xA1;
            float nxB0 = yB0 + e0, nxB1 = yB1 + e1;
            float nyB0 = gB0 - xB0, nyB1 = gB1 - xB1;
            xA0 = nxA0; xA1 = nxA1; yA0 = nyA0; yA1 = nyA1;
            xB0 = nxB0; xB1 = nxB1; yB0 = nyB0; yB1 = nyB1;
        }
    }

    out[idx] = make_float4(xA0, xA1, yA0, yA1);
    if (hasB)
        out[idx2] = make_float4(xB0, xB1, yB0, yB1);
}

extern "C" void kernel_launch(void* const* d_in, const int* in_sizes, int n_in,
                              void* d_out, int out_size)
{
    const float* r        = (const float*)d_in[0];
    const float* theta0   = (const float*)d_in[1];
    const float* psi_Win  = (const float*)d_in[2];
    const float* psi_Wout = (const float*)d_in[3];
    const float* psi_b    = (const float*)d_in[4];
    const float* psi_eta  = (const float*)d_in[5];
    const float* ni_Win   = (const float*)d_in[6];
    const float* ni_Wout  = (const float*)d_in[7];
    const float* ni_b     = (const float*)d_in[8];
    const float* ni_eta   = (const float*)d_in[9];

    int B = in_sizes[0] / 4;
    int half = (B + 1) / 2;

    prep_kernel<<<1, 1024>>>(theta0, psi_Win, psi_Wout, psi_b, psi_eta,
                             ni_Win, ni_Wout, ni_b, ni_eta);

    int threads = 256;
    int blocks = (half + threads - 1) / threads;
    gyro_kernel<<<blocks, threads>>>((const float4*)r, (float4*)d_out, B, half);
}